// round 3
// baseline (speedup 1.0000x reference)
#include <cuda_runtime.h>

// ---------------- problem constants ----------------
#define N_TOK   1024
#define TZ      128          // z channels
#define TD      64           // hidden dim
#define NB      38           // num bins
#define EPSF    1e-5f

// ---------------- kernel tiling ----------------
#define TM      32           // pairs (rows) per tile
#define THREADS 256
#define NBLOCKS 296          // 2 per SM on 148-SM B300 die (persistent)
#define ZSTR    132          // zs row stride (floats), padded
#define VSTR    68           // Vs row stride (floats), padded

typedef unsigned long long u64;

// preprocessed weights (written by prep kernel each launch; deterministic)
__device__ float g_W1[TZ * TD];   // [c][d] = Wz[d][c] * z_gamma[c]
__device__ float g_W2t[TD * TZ];  // [d][c] = Wu[c][d]
__device__ float g_S[TD];         // sum_c W1[c][d]
__device__ float g_T[TD];         // sum_c Wz[d][c] * z_beta[c]

// ---------------- packed f32x2 helpers ----------------
__device__ __forceinline__ u64 dup2(float x) {
    u64 r;
    asm("mov.b64 %0, {%1, %1};" : "=l"(r) : "r"(__float_as_int(x)));
    return r;
}
__device__ __forceinline__ void ffma2(u64 &acc, u64 a, u64 b) {
    asm("fma.rn.f32x2 %0, %1, %2, %0;" : "+l"(acc) : "l"(a), "l"(b));
}
__device__ __forceinline__ float2 unpk(u64 v) {
    unsigned lo, hi;
    asm("mov.b64 {%0, %1}, %2;" : "=r"(lo), "=r"(hi) : "l"(v));
    return make_float2(__uint_as_float(lo), __uint_as_float(hi));
}

// ---------------- prep kernel ----------------
__global__ void prep_kernel(const float* __restrict__ Wz, const float* __restrict__ zg,
                            const float* __restrict__ zb, const float* __restrict__ Wu) {
    int t = threadIdx.x;
    for (int s = t; s < TZ * TD; s += THREADS) {
        int c = s / TD, d = s % TD;
        g_W1[s] = Wz[d * TZ + c] * zg[c];
    }
    for (int s = t; s < TD * TZ; s += THREADS) {
        int d = s / TZ, c = s % TZ;
        g_W2t[s] = Wu[c * TD + d];
    }
    __syncthreads();
    if (t < TD) {
        float S = 0.f, T = 0.f;
        for (int c = 0; c < TZ; c++) {
            S += g_W1[c * TD + t];
            T += Wz[t * TZ + c] * zb[c];
        }
        g_S[t] = S;
        g_T[t] = T;
    }
}

// ---------------- main fused kernel ----------------
__global__ __launch_bounds__(THREADS, 2)
void token_distance_kernel(const float* __restrict__ z, const float* __restrict__ cc,
                           const float* __restrict__ tdm, const float* __restrict__ Wa,
                           const float* __restrict__ vgam, const float* __restrict__ vbet,
                           float* __restrict__ out) {
    extern __shared__ float sm[];
    float* W1s  = sm;                   // 8192 : [c][d]
    float* W2s  = W1s + TZ * TD;        // 8192 : [d][c]
    float* zs   = W2s + TD * TZ;        // TM*ZSTR
    float* Vs   = zs + TM * ZSTR;       // TM*VSTR
    float* Was  = Vs + TM * VSTR;       // NB*TD : [bin][d]
    float* Ss   = Was + NB * TD;        // 64
    float* Ts   = Ss + TD;              // 64
    float* vgs  = Ts + TD;              // 64
    float* vbs  = vgs + TD;             // 64
    float* m1s  = vbs + TD;             // 32
    float* rs1s = m1s + TM;             // 32
    float* m2s  = rs1s + TM;            // 32
    float* rs2s = m2s + TM;             // 32
    float* msks = rs2s + TM;            // 32
    int*   idxs = (int*)(msks + TM);    // 32

    const int t = threadIdx.x;

    // per-block weight staging (once; blocks are persistent)
    for (int s = t; s < TZ * TD; s += THREADS) W1s[s] = g_W1[s];
    for (int s = t; s < TD * TZ; s += THREADS) W2s[s] = g_W2t[s];
    for (int s = t; s < NB * TD; s += THREADS) {
        int k = s >> 6, d = s & 63;
        Was[s] = Wa[d * NB + k];
    }
    if (t < TD) {
        Ss[t] = g_S[t]; Ts[t] = g_T[t];
        vgs[t] = vgam[t]; vbs[t] = vbet[t];
    }

    const int tx = t & 15, ty = t >> 4;
    const int d0 = tx * 4;           // GEMM1 output cols (conflict-free groups)
    const int c0 = tx * 4;           // GEMM2 output cols (plus +64 group)
    const int r0 = ty * 2;           // 2 rows per thread
    const int rr = t >> 3, part = t & 7;   // stats mapping: 8 threads/row

    const int NTILES = (N_TOK * N_TOK) / TM;
    for (int tile = blockIdx.x; tile < NTILES; tile += gridDim.x) {
        const int base_p = tile * TM;
        __syncthreads();   // guard zs/Vs reuse across iterations

        // ---- coalesced z tile load ----
        const float4* zg4 = (const float4*)(z + (size_t)base_p * TZ);
        #pragma unroll
        for (int i = 0; i < 4; i++) {
            int e = i * THREADS + t;           // 0..1023 float4
            float4 v = zg4[e];
            int r = e >> 5, c4 = e & 31;
            *(float4*)&zs[r * ZSTR + c4 * 4] = v;
        }
        __syncthreads();

        // ---- row stats (LN1) + distance bin ----
        {
            float s = 0.f, q = 0.f;
            #pragma unroll
            for (int i = 0; i < 4; i++) {
                float4 v = *(const float4*)&zs[rr * ZSTR + part * 16 + i * 4];
                s += v.x + v.y + v.z + v.w;
                q += v.x * v.x + v.y * v.y + v.z * v.z + v.w * v.w;
            }
            #pragma unroll
            for (int o = 1; o < 8; o <<= 1) {
                s += __shfl_xor_sync(0xffffffffu, s, o);
                q += __shfl_xor_sync(0xffffffffu, q, o);
            }
            if (part == 0) {
                float m = s * (1.f / TZ);
                float var = fmaxf(q * (1.f / TZ) - m * m, 0.f);
                m1s[rr] = m;
                rs1s[rr] = rsqrtf(var + EPSF);
                int p = base_p + rr;
                int i0 = p >> 10, j0 = p & (N_TOK - 1);
                float dx = cc[i0 * 3 + 0] - cc[j0 * 3 + 0];
                float dy = cc[i0 * 3 + 1] - cc[j0 * 3 + 1];
                float dz = cc[i0 * 3 + 2] - cc[j0 * 3 + 2];
                float dist = sqrtf(dx * dx + dy * dy + dz * dz);
                int idx = 0;
                #pragma unroll
                for (int k = 0; k < NB - 1; k++) {
                    float b = (float)(3.25 + k * (47.5 / 36.0));
                    idx += (dist > b) ? 1 : 0;
                }
                idxs[rr] = idx;
                msks[rr] = tdm[p];
            }
        }
        __syncthreads();

        // ---- GEMM1: V[TM][TD] = z @ W1, packed f32x2, 2 rows x 4 cols/thread ----
        {
            u64 a00 = 0, a01 = 0, a10 = 0, a11 = 0;
            #pragma unroll 8
            for (int cb = 0; cb < TZ; cb += 4) {
                float4 z0 = *(const float4*)&zs[r0 * ZSTR + cb];
                float4 z1 = *(const float4*)&zs[(r0 + 1) * ZSTR + cb];
                #define G1STEP(K, ZC0, ZC1) { \
                    ulonglong2 w = *(const ulonglong2*)&W1s[(cb + K) * TD + d0]; \
                    u64 p0 = dup2(ZC0); u64 p1 = dup2(ZC1); \
                    ffma2(a00, w.x, p0); ffma2(a01, w.y, p0); \
                    ffma2(a10, w.x, p1); ffma2(a11, w.y, p1); }
                G1STEP(0, z0.x, z1.x)
                G1STEP(1, z0.y, z1.y)
                G1STEP(2, z0.z, z1.z)
                G1STEP(3, z0.w, z1.w)
                #undef G1STEP
            }
            // epilogue: fold LN1 affine + S,T + distance-bin column
            float2 q00 = unpk(a00), q01 = unpk(a01), q10 = unpk(a10), q11 = unpk(a11);
            float4 Sv = *(const float4*)&Ss[d0];
            float4 Tv = *(const float4*)&Ts[d0];
            {
                int r = r0;
                float m1 = m1s[r], r1 = rs1s[r], mk = msks[r];
                float4 wa = *(const float4*)&Was[idxs[r] * TD + d0];
                float4 res;
                res.x = r1 * (q00.x - m1 * Sv.x) + Tv.x + mk * wa.x;
                res.y = r1 * (q00.y - m1 * Sv.y) + Tv.y + mk * wa.y;
                res.z = r1 * (q01.x - m1 * Sv.z) + Tv.z + mk * wa.z;
                res.w = r1 * (q01.y - m1 * Sv.w) + Tv.w + mk * wa.w;
                *(float4*)&Vs[r * VSTR + d0] = res;
            }
            {
                int r = r0 + 1;
                float m1 = m1s[r], r1 = rs1s[r], mk = msks[r];
                float4 wa = *(const float4*)&Was[idxs[r] * TD + d0];
                float4 res;
                res.x = r1 * (q10.x - m1 * Sv.x) + Tv.x + mk * wa.x;
                res.y = r1 * (q10.y - m1 * Sv.y) + Tv.y + mk * wa.y;
                res.z = r1 * (q11.x - m1 * Sv.z) + Tv.z + mk * wa.z;
                res.w = r1 * (q11.y - m1 * Sv.w) + Tv.w + mk * wa.w;
                *(float4*)&Vs[r * VSTR + d0] = res;
            }
        }
        __syncthreads();

        // ---- stats2 (LN over 64, exact for the v+v doubling via 4*var) ----
        {
            float s = 0.f, q = 0.f;
            float4 a4 = *(const float4*)&Vs[rr * VSTR + part * 8];
            float4 b4 = *(const float4*)&Vs[rr * VSTR + part * 8 + 4];
            s = a4.x + a4.y + a4.z + a4.w + b4.x + b4.y + b4.z + b4.w;
            q = a4.x * a4.x + a4.y * a4.y + a4.z * a4.z + a4.w * a4.w
              + b4.x * b4.x + b4.y * b4.y + b4.z * b4.z + b4.w * b4.w;
            #pragma unroll
            for (int o = 1; o < 8; o <<= 1) {
                s += __shfl_xor_sync(0xffffffffu, s, o);
                q += __shfl_xor_sync(0xffffffffu, q, o);
            }
            if (part == 0) {
                float m = s * (1.f / TD);
                float var = fmaxf(q * (1.f / TD) - m * m, 0.f);
                m2s[rr] = m;
                rs2s[rr] = rsqrtf(4.f * var + EPSF);   // LN of (v+v): 2(v-m)/sqrt(4var+eps)
            }
        }
        __syncthreads();

        // ---- normalize + relu in place ----
        {
            float m = m2s[rr];
            float sc = 2.f * rs2s[rr];
            int db = part * 8;
            float4 a4 = *(const float4*)&Vs[rr * VSTR + db];
            float4 b4 = *(const float4*)&Vs[rr * VSTR + db + 4];
            a4.x = fmaxf(fmaf((a4.x - m) * sc, vgs[db + 0], vbs[db + 0]), 0.f);
            a4.y = fmaxf(fmaf((a4.y - m) * sc, vgs[db + 1], vbs[db + 1]), 0.f);
            a4.z = fmaxf(fmaf((a4.z - m) * sc, vgs[db + 2], vbs[db + 2]), 0.f);
            a4.w = fmaxf(fmaf((a4.w - m) * sc, vgs[db + 3], vbs[db + 3]), 0.f);
            b4.x = fmaxf(fmaf((b4.x - m) * sc, vgs[db + 4], vbs[db + 4]), 0.f);
            b4.y = fmaxf(fmaf((b4.y - m) * sc, vgs[db + 5], vbs[db + 5]), 0.f);
            b4.z = fmaxf(fmaf((b4.z - m) * sc, vgs[db + 6], vbs[db + 6]), 0.f);
            b4.w = fmaxf(fmaf((b4.w - m) * sc, vgs[db + 7], vbs[db + 7]), 0.f);
            *(float4*)&Vs[rr * VSTR + db] = a4;
            *(float4*)&Vs[rr * VSTR + db + 4] = b4;
        }
        __syncthreads();

        // ---- GEMM2: U[TM][TZ] = relu(Vn) @ W2t, 2 rows x 8 cols/thread ----
        {
            u64 b00 = 0, b01 = 0, b02 = 0, b03 = 0;
            u64 b10 = 0, b11 = 0, b12 = 0, b13 = 0;
            #pragma unroll 4
            for (int db = 0; db < TD; db += 4) {
                float4 v0 = *(const float4*)&Vs[r0 * VSTR + db];
                float4 v1 = *(const float4*)&Vs[(r0 + 1) * VSTR + db];
                #define G2STEP(K, VC0, VC1) { \
                    ulonglong2 wA = *(const ulonglong2*)&W2s[(db + K) * TZ + c0]; \
                    ulonglong2 wB = *(const ulonglong2*)&W2s[(db + K) * TZ + c0 + 64]; \
                    u64 p0 = dup2(VC0); u64 p1 = dup2(VC1); \
                    ffma2(b00, wA.x, p0); ffma2(b01, wA.y, p0); \
                    ffma2(b02, wB.x, p0); ffma2(b03, wB.y, p0); \
                    ffma2(b10, wA.x, p1); ffma2(b11, wA.y, p1); \
                    ffma2(b12, wB.x, p1); ffma2(b13, wB.y, p1); }
                G2STEP(0, v0.x, v1.x)
                G2STEP(1, v0.y, v1.y)
                G2STEP(2, v0.z, v1.z)
                G2STEP(3, v0.w, v1.w)
                #undef G2STEP
            }
            {
                float2 u0 = unpk(b00), u1 = unpk(b01), u2 = unpk(b02), u3 = unpk(b03);
                float* o = out + (size_t)(base_p + r0) * TZ;
                *(float4*)&o[c0]      = make_float4(u0.x, u0.y, u1.x, u1.y);
                *(float4*)&o[c0 + 64] = make_float4(u2.x, u2.y, u3.x, u3.y);
            }
            {
                float2 u0 = unpk(b10), u1 = unpk(b11), u2 = unpk(b12), u3 = unpk(b13);
                float* o = out + (size_t)(base_p + r0 + 1) * TZ;
                *(float4*)&o[c0]      = make_float4(u0.x, u0.y, u1.x, u1.y);
                *(float4*)&o[c0 + 64] = make_float4(u2.x, u2.y, u3.x, u3.y);
            }
        }
    }
}

// ---------------- launch ----------------
static const int SMEM_FLOATS =
    TZ * TD + TD * TZ + TM * ZSTR + TM * VSTR + NB * TD + 4 * TD + 6 * TM;

extern "C" void kernel_launch(void* const* d_in, const int* in_sizes, int n_in,
                              void* d_out, int out_size) {
    const float* z    = (const float*)d_in[0];   // (1,1024,1024,128)
    const float* cc   = (const float*)d_in[1];   // (1,1024,3)
    const float* tdm  = (const float*)d_in[2];   // (1,1024,1024)
    // d_in[3] = pair_mask (unused by reference)
    const float* Wz   = (const float*)d_in[4];   // (64,128)
    const float* Wa   = (const float*)d_in[5];   // (64,38)
    const float* Wu   = (const float*)d_in[6];   // (128,64)
    const float* zg   = (const float*)d_in[7];   // (128)
    const float* zb   = (const float*)d_in[8];   // (128)
    const float* vg   = (const float*)d_in[9];   // (64)
    const float* vb   = (const float*)d_in[10];  // (64)
    float* out = (float*)d_out;

    size_t smem_bytes = (size_t)SMEM_FLOATS * sizeof(float);
    cudaFuncSetAttribute(token_distance_kernel,
                         cudaFuncAttributeMaxDynamicSharedMemorySize, (int)smem_bytes);

    prep_kernel<<<1, THREADS>>>(Wz, zg, zb, Wu);
    token_distance_kernel<<<NBLOCKS, THREADS, smem_bytes>>>(z, cc, tdm, Wa, vg, vb, out);
}

// round 4
// speedup vs baseline: 1.3188x; 1.3188x over previous
#include <cuda_runtime.h>

// ---------------- problem constants ----------------
#define N_TOK   1024
#define TZ      128          // z channels
#define TD      64           // hidden dim
#define NB      38           // num bins
#define EPSF    1e-5f

// ---------------- kernel tiling ----------------
#define TM      64           // pairs (rows) per tile
#define THREADS 256
#define NBLOCKS 152          // 1 per SM on 152-SM GB300 (persistent)
#define ZSTR    132          // zs row stride (floats), padded
#define VSTR    68           // Vs row stride (floats), padded

typedef unsigned long long u64;

// preprocessed weights (written by prep kernel each launch; deterministic)
__device__ float g_W1[TZ * TD];   // [c][d] = Wz[d][c] * z_gamma[c]
__device__ float g_W2t[TD * TZ];  // [d][c] = Wu[c][d]
__device__ float g_S[TD];         // sum_c W1[c][d]
__device__ float g_T[TD];         // sum_c Wz[d][c] * z_beta[c]

// ---------------- packed f32x2 helpers ----------------
__device__ __forceinline__ u64 dup2(float x) {
    u64 r;
    asm("mov.b64 %0, {%1, %1};" : "=l"(r) : "r"(__float_as_int(x)));
    return r;
}
__device__ __forceinline__ void ffma2(u64 &acc, u64 a, u64 b) {
    asm("fma.rn.f32x2 %0, %1, %2, %0;" : "+l"(acc) : "l"(a), "l"(b));
}
__device__ __forceinline__ float2 unpk(u64 v) {
    unsigned lo, hi;
    asm("mov.b64 {%0, %1}, %2;" : "=r"(lo), "=r"(hi) : "l"(v));
    return make_float2(__uint_as_float(lo), __uint_as_float(hi));
}

// ---------------- cp.async helpers ----------------
__device__ __forceinline__ void cpa16(float* dst, const float* src) {
    unsigned a = (unsigned)__cvta_generic_to_shared(dst);
    asm volatile("cp.async.cg.shared.global [%0], [%1], 16;" :: "r"(a), "l"(src));
}
__device__ __forceinline__ void cpa_commit() {
    asm volatile("cp.async.commit_group;");
}
__device__ __forceinline__ void cpa_wait_all() {
    asm volatile("cp.async.wait_group 0;" ::: "memory");
}

// ---------------- prep kernel ----------------
__global__ void prep_kernel(const float* __restrict__ Wz, const float* __restrict__ zg,
                            const float* __restrict__ zb, const float* __restrict__ Wu) {
    int t = threadIdx.x;
    for (int s = t; s < TZ * TD; s += THREADS) {
        int c = s / TD, d = s % TD;
        g_W1[s] = Wz[d * TZ + c] * zg[c];
    }
    for (int s = t; s < TD * TZ; s += THREADS) {
        int d = s / TZ, c = s % TZ;
        g_W2t[s] = Wu[c * TD + d];
    }
    __syncthreads();
    if (t < TD) {
        float S = 0.f, T = 0.f;
        for (int c = 0; c < TZ; c++) {
            S += g_W1[c * TD + t];
            T += Wz[t * TZ + c] * zb[c];
        }
        g_S[t] = S;
        g_T[t] = T;
    }
}

// ---------------- main fused kernel ----------------
__global__ __launch_bounds__(THREADS, 1)
void token_distance_kernel(const float* __restrict__ z, const float* __restrict__ cc,
                           const float* __restrict__ tdm, const float* __restrict__ Wa,
                           const float* __restrict__ vgam, const float* __restrict__ vbet,
                           float* __restrict__ out) {
    extern __shared__ float sm[];
    float* W1s  = sm;                   // 8192 : [c][d]
    float* W2s  = W1s + TZ * TD;        // 8192 : [d][c]
    float* zs0  = W2s + TD * TZ;        // TM*ZSTR (double buffered)
    float* zs1  = zs0 + TM * ZSTR;
    float* Vs   = zs1 + TM * ZSTR;      // TM*VSTR
    float* Was  = Vs + TM * VSTR;       // NB*TD : [bin][d]
    float* Ss   = Was + NB * TD;        // 64
    float* Ts   = Ss + TD;              // 64
    float* vgs  = Ts + TD;              // 64
    float* vbs  = vgs + TD;             // 64
    float* m1s  = vbs + TD;             // TM
    float* rs1s = m1s + TM;             // TM
    float* m2s  = rs1s + TM;            // TM
    float* rs2s = m2s + TM;             // TM
    float* msks = rs2s + TM;            // TM
    int*   idxs = (int*)(msks + TM);    // TM

    const int t = threadIdx.x;

    // per-block weight staging (once; blocks are persistent)
    for (int s = t; s < TZ * TD; s += THREADS) W1s[s] = g_W1[s];
    for (int s = t; s < TD * TZ; s += THREADS) W2s[s] = g_W2t[s];
    for (int s = t; s < NB * TD; s += THREADS) {
        int k = s >> 6, d = s & 63;
        Was[s] = Wa[d * NB + k];
    }
    if (t < TD) {
        Ss[t] = g_S[t]; Ts[t] = g_T[t];
        vgs[t] = vgam[t]; vbs[t] = vbet[t];
    }

    const int tx = t & 15, ty = t >> 4;
    const int d0 = tx * 4;           // GEMM1 output cols
    const int c0 = tx * 4;           // GEMM2 output cols (plus +64 group)
    const int r0 = ty * 4;           // 4 rows per thread
    const int rr = t >> 2, part = t & 3;   // stats mapping: 4 threads/row

    const int NTILES = (N_TOK * N_TOK) / TM;   // 16384

    float* zbuf[2] = { zs0, zs1 };
    int cur = 0;

    // prefetch first tile
    int tile0 = blockIdx.x;
    if (tile0 < NTILES) {
        const float* zg0 = z + (size_t)tile0 * TM * TZ;
        #pragma unroll
        for (int i = 0; i < 8; i++) {
            int e = i * THREADS + t;           // 0..2047 float4
            int r = e >> 5, c4 = e & 31;
            cpa16(&zbuf[0][r * ZSTR + c4 * 4], zg0 + e * 4);
        }
        cpa_commit();
    }

    for (int tile = tile0; tile < NTILES; tile += NBLOCKS) {
        const int base_p = tile * TM;

        cpa_wait_all();
        __syncthreads();          // z(cur) ready; also guards Vs/msks reuse
        float* zc = zbuf[cur];

        // ---- row stats (LN1) ----
        {
            float s = 0.f, q = 0.f;
            const float* zrow = &zc[rr * ZSTR + part * 32];
            #pragma unroll
            for (int i = 0; i < 8; i++) {
                float4 v = *(const float4*)&zrow[i * 4];
                s += v.x + v.y + v.z + v.w;
                q += v.x * v.x + v.y * v.y + v.z * v.z + v.w * v.w;
            }
            #pragma unroll
            for (int o = 1; o < 4; o <<= 1) {
                s += __shfl_xor_sync(0xffffffffu, s, o);
                q += __shfl_xor_sync(0xffffffffu, q, o);
            }
            if (part == 0) {
                float m = s * (1.f / TZ);
                float var = fmaxf(q * (1.f / TZ) - m * m, 0.f);
                m1s[rr] = m;
                rs1s[rr] = rsqrtf(var + EPSF);
            }
        }
        // ---- distance bin + mask (independent of z) ----
        if (t < TM) {
            int p = base_p + t;
            int i0 = p >> 10, j0 = p & (N_TOK - 1);
            float dx = cc[i0 * 3 + 0] - cc[j0 * 3 + 0];
            float dy = cc[i0 * 3 + 1] - cc[j0 * 3 + 1];
            float dz = cc[i0 * 3 + 2] - cc[j0 * 3 + 2];
            float dist = sqrtf(dx * dx + dy * dy + dz * dz);
            int idx = 0;
            #pragma unroll
            for (int k = 0; k < NB - 1; k++) {
                float b = (float)(3.25 + k * (47.5 / 36.0));
                idx += (dist > b) ? 1 : 0;
            }
            idxs[t] = idx;
            msks[t] = tdm[p];
        }
        __syncthreads();

        // ---- GEMM1: V[TM][TD] = z @ W1, 4 rows x 4 cols/thread ----
        {
            u64 a00 = 0, a01 = 0, a10 = 0, a11 = 0;
            u64 a20 = 0, a21 = 0, a30 = 0, a31 = 0;
            #pragma unroll 4
            for (int cb = 0; cb < TZ; cb += 4) {
                float4 z0 = *(const float4*)&zc[(r0 + 0) * ZSTR + cb];
                float4 z1 = *(const float4*)&zc[(r0 + 1) * ZSTR + cb];
                float4 z2 = *(const float4*)&zc[(r0 + 2) * ZSTR + cb];
                float4 z3 = *(const float4*)&zc[(r0 + 3) * ZSTR + cb];
                #define G1STEP(K, S0, S1, S2, S3) { \
                    ulonglong2 w = *(const ulonglong2*)&W1s[(cb + K) * TD + d0]; \
                    u64 p0 = dup2(S0), p1 = dup2(S1), p2 = dup2(S2), p3 = dup2(S3); \
                    ffma2(a00, w.x, p0); ffma2(a01, w.y, p0); \
                    ffma2(a10, w.x, p1); ffma2(a11, w.y, p1); \
                    ffma2(a20, w.x, p2); ffma2(a21, w.y, p2); \
                    ffma2(a30, w.x, p3); ffma2(a31, w.y, p3); }
                G1STEP(0, z0.x, z1.x, z2.x, z3.x)
                G1STEP(1, z0.y, z1.y, z2.y, z3.y)
                G1STEP(2, z0.z, z1.z, z2.z, z3.z)
                G1STEP(3, z0.w, z1.w, z2.w, z3.w)
                #undef G1STEP
            }
            // epilogue: fold LN1 affine + S,T + distance-bin column
            float4 Sv = *(const float4*)&Ss[d0];
            float4 Tv = *(const float4*)&Ts[d0];
            u64 accs[4][2] = {{a00, a01}, {a10, a11}, {a20, a21}, {a30, a31}};
            #pragma unroll
            for (int i = 0; i < 4; i++) {
                int r = r0 + i;
                float m1 = m1s[r], r1 = rs1s[r], mk = msks[r];
                float4 wa = *(const float4*)&Was[idxs[r] * TD + d0];
                float2 qa = unpk(accs[i][0]), qb = unpk(accs[i][1]);
                float4 res;
                res.x = r1 * (qa.x - m1 * Sv.x) + Tv.x + mk * wa.x;
                res.y = r1 * (qa.y - m1 * Sv.y) + Tv.y + mk * wa.y;
                res.z = r1 * (qb.x - m1 * Sv.z) + Tv.z + mk * wa.z;
                res.w = r1 * (qb.y - m1 * Sv.w) + Tv.w + mk * wa.w;
                *(float4*)&Vs[r * VSTR + d0] = res;
            }
        }
        __syncthreads();

        // ---- prefetch next tile's z into the other buffer ----
        {
            int nt = tile + NBLOCKS;
            if (nt < NTILES) {
                const float* zgN = z + (size_t)nt * TM * TZ;
                float* zn = zbuf[cur ^ 1];
                #pragma unroll
                for (int i = 0; i < 8; i++) {
                    int e = i * THREADS + t;
                    int r = e >> 5, c4 = e & 31;
                    cpa16(&zn[r * ZSTR + c4 * 4], zgN + e * 4);
                }
                cpa_commit();
            }
        }

        // ---- stats2 (LN over 64; exact v+v doubling via 4*var) ----
        {
            float s = 0.f, q = 0.f;
            const float* vrow = &Vs[rr * VSTR + part * 16];
            #pragma unroll
            for (int i = 0; i < 4; i++) {
                float4 v = *(const float4*)&vrow[i * 4];
                s += v.x + v.y + v.z + v.w;
                q += v.x * v.x + v.y * v.y + v.z * v.z + v.w * v.w;
            }
            #pragma unroll
            for (int o = 1; o < 4; o <<= 1) {
                s += __shfl_xor_sync(0xffffffffu, s, o);
                q += __shfl_xor_sync(0xffffffffu, q, o);
            }
            if (part == 0) {
                float m = s * (1.f / TD);
                float var = fmaxf(q * (1.f / TD) - m * m, 0.f);
                m2s[rr] = m;
                rs2s[rr] = rsqrtf(4.f * var + EPSF);   // LN of (v+v)
            }
        }
        __syncthreads();

        // ---- normalize + relu in place ----
        {
            float m = m2s[rr];
            float sc = 2.f * rs2s[rr];
            int db = part * 16;
            #pragma unroll
            for (int i = 0; i < 4; i++) {
                float4 v = *(const float4*)&Vs[rr * VSTR + db + i * 4];
                float4 g = *(const float4*)&vgs[db + i * 4];
                float4 b = *(const float4*)&vbs[db + i * 4];
                v.x = fmaxf(fmaf((v.x - m) * sc, g.x, b.x), 0.f);
                v.y = fmaxf(fmaf((v.y - m) * sc, g.y, b.y), 0.f);
                v.z = fmaxf(fmaf((v.z - m) * sc, g.z, b.z), 0.f);
                v.w = fmaxf(fmaf((v.w - m) * sc, g.w, b.w), 0.f);
                *(float4*)&Vs[rr * VSTR + db + i * 4] = v;
            }
        }
        __syncthreads();

        // ---- GEMM2: U[TM][TZ] = relu(Vn) @ W2t, 4 rows x 8 cols/thread ----
        {
            u64 b0[4] = {0, 0, 0, 0};   // row 0: cols c0..c0+3, c0+64..c0+67
            u64 b1[4] = {0, 0, 0, 0};
            u64 b2[4] = {0, 0, 0, 0};
            u64 b3[4] = {0, 0, 0, 0};
            #pragma unroll 4
            for (int db = 0; db < TD; db += 4) {
                float4 v0 = *(const float4*)&Vs[(r0 + 0) * VSTR + db];
                float4 v1 = *(const float4*)&Vs[(r0 + 1) * VSTR + db];
                float4 v2 = *(const float4*)&Vs[(r0 + 2) * VSTR + db];
                float4 v3 = *(const float4*)&Vs[(r0 + 3) * VSTR + db];
                #define G2STEP(K, S0, S1, S2, S3) { \
                    ulonglong2 wA = *(const ulonglong2*)&W2s[(db + K) * TZ + c0]; \
                    ulonglong2 wB = *(const ulonglong2*)&W2s[(db + K) * TZ + c0 + 64]; \
                    u64 p0 = dup2(S0), p1 = dup2(S1), p2 = dup2(S2), p3 = dup2(S3); \
                    ffma2(b0[0], wA.x, p0); ffma2(b0[1], wA.y, p0); \
                    ffma2(b0[2], wB.x, p0); ffma2(b0[3], wB.y, p0); \
                    ffma2(b1[0], wA.x, p1); ffma2(b1[1], wA.y, p1); \
                    ffma2(b1[2], wB.x, p1); ffma2(b1[3], wB.y, p1); \
                    ffma2(b2[0], wA.x, p2); ffma2(b2[1], wA.y, p2); \
                    ffma2(b2[2], wB.x, p2); ffma2(b2[3], wB.y, p2); \
                    ffma2(b3[0], wA.x, p3); ffma2(b3[1], wA.y, p3); \
                    ffma2(b3[2], wB.x, p3); ffma2(b3[3], wB.y, p3); }
                G2STEP(0, v0.x, v1.x, v2.x, v3.x)
                G2STEP(1, v0.y, v1.y, v2.y, v3.y)
                G2STEP(2, v0.z, v1.z, v2.z, v3.z)
                G2STEP(3, v0.w, v1.w, v2.w, v3.w)
                #undef G2STEP
            }
            #define G2OUT(BI, ROW) { \
                float2 u0 = unpk(BI[0]), u1 = unpk(BI[1]); \
                float2 u2 = unpk(BI[2]), u3 = unpk(BI[3]); \
                float* o = out + (size_t)(base_p + (ROW)) * TZ; \
                *(float4*)&o[c0]      = make_float4(u0.x, u0.y, u1.x, u1.y); \
                *(float4*)&o[c0 + 64] = make_float4(u2.x, u2.y, u3.x, u3.y); }
            G2OUT(b0, r0 + 0)
            G2OUT(b1, r0 + 1)
            G2OUT(b2, r0 + 2)
            G2OUT(b3, r0 + 3)
            #undef G2OUT
        }
        cur ^= 1;
    }
}

// ---------------- launch ----------------
static const int SMEM_FLOATS =
    TZ * TD + TD * TZ + 2 * TM * ZSTR + TM * VSTR + NB * TD + 4 * TD + 6 * TM;

extern "C" void kernel_launch(void* const* d_in, const int* in_sizes, int n_in,
                              void* d_out, int out_size) {
    const float* z    = (const float*)d_in[0];   // (1,1024,1024,128)
    const float* cc   = (const float*)d_in[1];   // (1,1024,3)
    const float* tdm  = (const float*)d_in[2];   // (1,1024,1024)
    // d_in[3] = pair_mask (unused by reference)
    const float* Wz   = (const float*)d_in[4];   // (64,128)
    const float* Wa   = (const float*)d_in[5];   // (64,38)
    const float* Wu   = (const float*)d_in[6];   // (128,64)
    const float* zg   = (const float*)d_in[7];   // (128)
    const float* zb   = (const float*)d_in[8];   // (128)
    const float* vg   = (const float*)d_in[9];   // (64)
    const float* vb   = (const float*)d_in[10];  // (64)
    float* out = (float*)d_out;

    size_t smem_bytes = (size_t)SMEM_FLOATS * sizeof(float);
    cudaFuncSetAttribute(token_distance_kernel,
                         cudaFuncAttributeMaxDynamicSharedMemorySize, (int)smem_bytes);

    prep_kernel<<<1, THREADS>>>(Wz, zg, zb, Wu);
    token_distance_kernel<<<NBLOCKS, THREADS, smem_bytes>>>(z, cc, tdm, Wa, vg, vb, out);
}

// round 6
// speedup vs baseline: 3.1720x; 2.4052x over previous
#include <cuda_runtime.h>
#include <cstdint>

typedef uint32_t u32;

#define N_TOK 1024
#define TZ 128
#define TD 64
#define NB 38
#define EPSF 1e-5f
#define TM 128
#define THREADS 256
#define NBLOCKS 152
#define NTILES ((N_TOK * N_TOK) / TM)   // 8192

// smem strides (floats) — chosen for conflict-free fragment loads
#define ZSTR 132     // 132 % 32 == 4 -> A-fragment bank == lane
#define VSTR 68      // 68 % 32 == 4
#define W1STR 72     // 72 % 32 == 8 -> B-fragment conflict-free
#define W2STR 136    // 136 % 32 == 8

// smem float offsets
#define ZA0_F 0                       // z buf0 128x132
#define ZA1_F (TM * ZSTR)             // z buf1
#define W1_F  (2 * TM * ZSTR)         // W1'[k][n] 128x72
#define W2_F  (W1_F + TZ * W1STR)     // W2 [d][c] 64x136
#define WAS_F (W2_F + TD * W2STR)     // Wa [bin][d] 38x64
#define S_F   (WAS_F + NB * TD)
#define T_F   (S_F + TD)
#define VG_F  (T_F + TD)
#define VB_F  (VG_F + TD)
#define M1_F  (VB_F + TD)             // float2[128]
#define BM_F  (M1_F + 2 * TM)         // float2[128]
#define LN2_F (BM_F + 2 * TM)         // float4[128] (s,q per col-half)
#define SMEM_FLOATS (LN2_F + 4 * TM)  // 55424 floats = 221696 B

// ---------------- helpers ----------------
__device__ __forceinline__ float rna_tf32(float x) {
    u32 r;
    asm("cvt.rna.tf32.f32 %0, %1;" : "=r"(r) : "f"(x));
    return __uint_as_float(r);
}
__device__ __forceinline__ void cpa16(float* dst, const void* g) {
    u32 a = (u32)__cvta_generic_to_shared(dst);
    asm volatile("cp.async.cg.shared.global [%0], [%1], 16;" :: "r"(a), "l"(g));
}
__device__ __forceinline__ void cpa_commit() { asm volatile("cp.async.commit_group;"); }
__device__ __forceinline__ void cpa_wait1() { asm volatile("cp.async.wait_group 1;" ::: "memory"); }
__device__ __forceinline__ void cpa_wait0() { asm volatile("cp.async.wait_group 0;" ::: "memory"); }

// D += A(16x8,row) * B(8x8,col), tf32
__device__ __forceinline__ void mma8(float* c, const u32* a, u32 b0, u32 b1) {
    asm volatile(
        "mma.sync.aligned.m16n8k8.row.col.f32.tf32.tf32.f32 "
        "{%0,%1,%2,%3}, {%4,%5,%6,%7}, {%8,%9}, {%0,%1,%2,%3};"
        : "+f"(c[0]), "+f"(c[1]), "+f"(c[2]), "+f"(c[3])
        : "r"(a[0]), "r"(a[1]), "r"(a[2]), "r"(a[3]), "r"(b0), "r"(b1));
}
__device__ __forceinline__ u32 ldsf(const float* p) { return __float_as_uint(*p); }

// ---------------- main fused kernel ----------------
__global__ __launch_bounds__(THREADS, 1)
void td_kernel(const float* __restrict__ z, const float* __restrict__ cc,
               const float* __restrict__ tdm, const float* __restrict__ Wz,
               const float* __restrict__ Wa, const float* __restrict__ Wu,
               const float* __restrict__ zg, const float* __restrict__ zb,
               const float* __restrict__ vg, const float* __restrict__ vb,
               float* __restrict__ out)
{
    extern __shared__ float smf[];
    const int t = threadIdx.x;
    const int wid = t >> 5, lane = t & 31;
    const int g = lane >> 2, tg = lane & 3;

    // ---- prefetch first tile (overlaps weight staging) ----
    const int tile0 = blockIdx.x;
    {
        const float* src = z + (size_t)tile0 * TM * TZ;
        #pragma unroll
        for (int i = 0; i < 16; i++) {
            int e = i * THREADS + t;            // 0..4095 float4
            cpa16(&smf[ZA0_F + (e >> 5) * ZSTR + (e & 31) * 4], src + e * 4);
        }
        cpa_commit();
    }

    // ---- one-time weight staging ----
    for (int s = t; s < TZ * TD; s += THREADS) {        // W1'[k][n] = Wz[n][k]*zg[k]
        int k = s >> 6, n = s & 63;
        smf[W1_F + k * W1STR + n] = rna_tf32(Wz[n * TZ + k] * zg[k]);
    }
    for (int s = t; s < TD * TZ; s += THREADS) {        // W2[d][c] = Wu[c][d]
        int d = s >> 7, c = s & 127;
        smf[W2_F + d * W2STR + c] = rna_tf32(Wu[c * TD + d]);
    }
    for (int s = t; s < NB * TD; s += THREADS) {        // Was[bin][d]
        int k = s >> 6, d = s & 63;
        smf[WAS_F + k * TD + d] = Wa[d * NB + k];
    }
    if (t < TD) {
        float S = 0.f, T = 0.f;
        for (int k = 0; k < TZ; k++) {
            S += rna_tf32(Wz[t * TZ + k] * zg[k]);
            T += Wz[t * TZ + k] * zb[k];
        }
        smf[S_F + t] = S; smf[T_F + t] = T;
        smf[VG_F + t] = vg[t]; smf[VB_F + t] = vb[t];
    }

    const int rb = wid >> 1, ch = wid & 1;     // warp grid 4x2
    const int R1 = rb * 32, C1 = ch * 32;      // GEMM1 tile base
    const int C2 = ch * 64;                    // GEMM2 col base (rows same R1)

    int cur = 0;
    for (int tile = tile0; tile < NTILES; tile += NBLOCKS) {
        const int base_p = tile * TM;
        const int nt_idx = tile + NBLOCKS;
        float* zc = &smf[cur ? ZA1_F : ZA0_F];
        float* zn = &smf[cur ? ZA0_F : ZA1_F];

        // prefetch next tile, wait for current
        if (nt_idx < NTILES) {
            const float* src = z + (size_t)nt_idx * TM * TZ;
            #pragma unroll
            for (int i = 0; i < 16; i++) {
                int e = i * THREADS + t;
                cpa16(&zn[(e >> 5) * ZSTR + (e & 31) * 4], src + e * 4);
            }
            cpa_commit();
            cpa_wait1();
        } else {
            cpa_wait0();
        }
        __syncthreads();

        // ---- stats1 (exact f32) + in-place tf32 rounding ----
        {
            const int rr = t >> 1, part = t & 1;
            float* zrow = &zc[rr * ZSTR + part * 64];
            float s = 0.f, q = 0.f;
            #pragma unroll
            for (int i = 0; i < 16; i++) {
                float4* p = (float4*)&zrow[i * 4];
                float4 v = *p;
                s += v.x + v.y + v.z + v.w;
                q += v.x * v.x + v.y * v.y + v.z * v.z + v.w * v.w;
                v.x = rna_tf32(v.x); v.y = rna_tf32(v.y);
                v.z = rna_tf32(v.z); v.w = rna_tf32(v.w);
                *p = v;
            }
            s += __shfl_xor_sync(0xffffffffu, s, 1);
            q += __shfl_xor_sync(0xffffffffu, q, 1);
            if (!part) {
                float m = s * (1.f / TZ);
                float var = fmaxf(q * (1.f / TZ) - m * m, 0.f);
                ((float2*)&smf[M1_F])[rr] = make_float2(m, rsqrtf(var + EPSF));
            }
        }
        if (t < TM) {
            int p = base_p + t;
            int i0 = p >> 10, j0 = p & (N_TOK - 1);
            float dx = cc[i0 * 3 + 0] - cc[j0 * 3 + 0];
            float dy = cc[i0 * 3 + 1] - cc[j0 * 3 + 1];
            float dz = cc[i0 * 3 + 2] - cc[j0 * 3 + 2];
            float dist = sqrtf(dx * dx + dy * dy + dz * dz);
            int idx = 0;
            #pragma unroll
            for (int k = 0; k < NB - 1; k++) {
                float b = (float)(3.25 + k * (47.5 / 36.0));
                idx += (dist > b) ? 1 : 0;
            }
            ((float2*)&smf[BM_F])[t] = make_float2(__int_as_float(idx), tdm[p]);
        }
        __syncthreads();

        // ---- GEMM1: v[128x64] = z @ W1'^T, warp tile 32x32 ----
        float acc[2][4][4];
        #pragma unroll
        for (int a = 0; a < 2; a++)
            #pragma unroll
            for (int b = 0; b < 4; b++)
                #pragma unroll
                for (int cI = 0; cI < 4; cI++) acc[a][b][cI] = 0.f;

        #pragma unroll 4
        for (int ks = 0; ks < 16; ks++) {
            const int k0 = ks * 8;
            u32 afr[2][4];
            #pragma unroll
            for (int rt = 0; rt < 2; rt++) {
                const float* zr = &zc[(R1 + 16 * rt + g) * ZSTR + k0 + tg];
                afr[rt][0] = ldsf(zr);
                afr[rt][2] = ldsf(zr + 4);
                afr[rt][1] = ldsf(zr + 8 * ZSTR);
                afr[rt][3] = ldsf(zr + 8 * ZSTR + 4);
            }
            #pragma unroll
            for (int nt = 0; nt < 4; nt++) {
                const float* wr = &smf[W1_F + (k0 + tg) * W1STR + C1 + 8 * nt + g];
                u32 b0 = ldsf(wr);
                u32 b1 = ldsf(wr + 4 * W1STR);
                mma8(acc[0][nt], afr[0], b0, b1);
                mma8(acc[1][nt], afr[1], b0, b1);
            }
        }

        // ---- epilogue 1: LN1-fold + bin + LN2 partials (in place) ----
        float s2r[4], q2r[4];
        #pragma unroll
        for (int i = 0; i < 4; i++) {
            const int row = R1 + g + 8 * i;
            const int rt = i >> 1, cp = (i & 1) * 2;
            float2 mr = ((float2*)&smf[M1_F])[row];
            float2 bm = ((float2*)&smf[BM_F])[row];
            const int bin = __float_as_int(bm.x);
            const float mk = bm.y;
            float s2 = 0.f, q2 = 0.f;
            #pragma unroll
            for (int nt = 0; nt < 4; nt++) {
                const int col = C1 + 8 * nt + 2 * tg;
                float2 Sv = *(const float2*)&smf[S_F + col];
                float2 Tv = *(const float2*)&smf[T_F + col];
                float2 Wv = *(const float2*)&smf[WAS_F + bin * TD + col];
                float v0 = mr.y * (acc[rt][nt][cp]     - mr.x * Sv.x) + Tv.x + mk * Wv.x;
                float v1 = mr.y * (acc[rt][nt][cp + 1] - mr.x * Sv.y) + Tv.y + mk * Wv.y;
                acc[rt][nt][cp] = v0; acc[rt][nt][cp + 1] = v1;
                s2 += v0 + v1;
                q2 += v0 * v0 + v1 * v1;
            }
            s2 += __shfl_xor_sync(0xffffffffu, s2, 1);
            q2 += __shfl_xor_sync(0xffffffffu, q2, 1);
            s2 += __shfl_xor_sync(0xffffffffu, s2, 2);
            q2 += __shfl_xor_sync(0xffffffffu, q2, 2);
            s2r[i] = s2; q2r[i] = q2;
        }
        if (tg == 0) {
            #pragma unroll
            for (int i = 0; i < 4; i++) {
                const int row = R1 + g + 8 * i;
                *(float2*)&smf[LN2_F + row * 4 + ch * 2] = make_float2(s2r[i], q2r[i]);
            }
        }
        __syncthreads();

        // ---- LN2 finalize + relu + tf32 -> vn (aliases zc) ----
        float* vn = zc;   // stride VSTR, fits inside 128x132 region
        #pragma unroll
        for (int i = 0; i < 4; i++) {
            const int row = R1 + g + 8 * i;
            const int rt = i >> 1, cp = (i & 1) * 2;
            float4 o = *(const float4*)&smf[LN2_F + row * 4];
            float st = o.x + o.z, qt = o.y + o.w;
            float m2 = st * (1.f / TD);
            float var = fmaxf(qt * (1.f / TD) - m2 * m2, 0.f);
            float sc = 2.f * rsqrtf(4.f * var + EPSF);    // exact v+v doubling
            #pragma unroll
            for (int nt = 0; nt < 4; nt++) {
                const int col = C1 + 8 * nt + 2 * tg;
                float2 gv = *(const float2*)&smf[VG_F + col];
                float2 bv = *(const float2*)&smf[VB_F + col];
                float2 r;
                r.x = rna_tf32(fmaxf(fmaf((acc[rt][nt][cp]     - m2) * sc, gv.x, bv.x), 0.f));
                r.y = rna_tf32(fmaxf(fmaf((acc[rt][nt][cp + 1] - m2) * sc, gv.y, bv.y), 0.f));
                *(float2*)&vn[row * VSTR + col] = r;
            }
        }
        __syncthreads();

        // ---- GEMM2: u[128x128] = vn @ W2^T, warp tile 32x64 + direct STG ----
        float acc2[2][8][4];
        #pragma unroll
        for (int a = 0; a < 2; a++)
            #pragma unroll
            for (int b = 0; b < 8; b++)
                #pragma unroll
                for (int cI = 0; cI < 4; cI++) acc2[a][b][cI] = 0.f;

        #pragma unroll 2
        for (int ks = 0; ks < 8; ks++) {
            const int k0 = ks * 8;
            u32 afr[2][4];
            #pragma unroll
            for (int rt = 0; rt < 2; rt++) {
                const float* vr = &vn[(R1 + 16 * rt + g) * VSTR + k0 + tg];
                afr[rt][0] = ldsf(vr);
                afr[rt][2] = ldsf(vr + 4);
                afr[rt][1] = ldsf(vr + 8 * VSTR);
                afr[rt][3] = ldsf(vr + 8 * VSTR + 4);
            }
            #pragma unroll
            for (int nt = 0; nt < 8; nt++) {
                const float* wr = &smf[W2_F + (k0 + tg) * W2STR + C2 + 8 * nt + g];
                u32 b0 = ldsf(wr);
                u32 b1 = ldsf(wr + 4 * W2STR);
                mma8(acc2[0][nt], afr[0], b0, b1);
                mma8(acc2[1][nt], afr[1], b0, b1);
            }
        }
        // epilogue 2: STG.64 per C-pair (fills whole 32B sectors)
        #pragma unroll
        for (int rt = 0; rt < 2; rt++) {
            const int ra = base_p + R1 + 16 * rt + g;
            #pragma unroll
            for (int nt = 0; nt < 8; nt++) {
                const int col = C2 + 8 * nt + 2 * tg;
                *(float2*)&out[(size_t)ra * TZ + col] =
                    make_float2(acc2[rt][nt][0], acc2[rt][nt][1]);
                *(float2*)&out[(size_t)(ra + 8) * TZ + col] =
                    make_float2(acc2[rt][nt][2], acc2[rt][nt][3]);
            }
        }
        cur ^= 1;
    }
}

// ---------------- launch ----------------
extern "C" void kernel_launch(void* const* d_in, const int* in_sizes, int n_in,
                              void* d_out, int out_size) {
    const float* z   = (const float*)d_in[0];   // (1,1024,1024,128)
    const float* cc  = (const float*)d_in[1];   // (1,1024,3)
    const float* tdm = (const float*)d_in[2];   // (1,1024,1024)
    // d_in[3] = pair_mask (unused by reference)
    const float* Wz  = (const float*)d_in[4];   // (64,128)
    const float* Wa  = (const float*)d_in[5];   // (64,38)
    const float* Wu  = (const float*)d_in[6];   // (128,64)
    const float* zg  = (const float*)d_in[7];   // (128)
    const float* zb  = (const float*)d_in[8];   // (128)
    const float* vg  = (const float*)d_in[9];   // (64)
    const float* vb  = (const float*)d_in[10];  // (64)
    float* out = (float*)d_out;

    size_t smem_bytes = (size_t)SMEM_FLOATS * sizeof(float);
    cudaFuncSetAttribute(td_kernel, cudaFuncAttributeMaxDynamicSharedMemorySize, (int)smem_bytes);
    td_kernel<<<NBLOCKS, THREADS, smem_bytes>>>(z, cc, tdm, Wz, Wa, Wu, zg, zb, vg, vb, out);
}